// round 5
// baseline (speedup 1.0000x reference)
#include <cuda_runtime.h>
#include <cstdint>

// OneHotEncoder: per-row token histogram (skip pad_idx=0) -> float counts.
// tokens: [B, T] int32, out: [B, 32000] float32.
//
// R5: fused zero + L2-atomic scatter, NO shared memory. The smem-atomic
// family has a ~5us chip floor (524K token-lanes x 2cyc ATOMS / 148 SMs);
// L2-side REDG is cheaper. R3's global-scatter failed because
// cudaMemsetAsync left the output non-L2-resident (DRAM=36%). Here each
// CTA (b,s) EXCLUSIVELY owns vocab quarter s of row b:
//   1) zeroes its 32KB slice with st.global.cg (allocates lines in L2)
//   2) __syncthreads + __threadfence (own stores ordered before own atomics)
//   3) scans row b's tokens, red.global.add.f32 for in-range non-pad tokens.
// No cross-CTA address overlap -> no inter-CTA ordering needed. Output is
// written once (zero) + sparse RMW, all L2-resident. Column 0 stays zero.

constexpr int VOCAB    = 32000;
constexpr int SPLIT    = 4;
constexpr int BINS     = VOCAB / SPLIT;   // 8000 floats = 32000 B per slice
constexpr int NTHREADS = 256;

__global__ __launch_bounds__(NTHREADS)
void onehot_zero_scatter_kernel(const int4* __restrict__ tokens4,
                                float* __restrict__ out,
                                int vecs_per_row)   // T/4
{
    const int cta = blockIdx.x;
    const int s   = cta & (SPLIT - 1);       // vocab slice index
    const int b   = cta >> 2;                // row index
    const int lo  = s * BINS;
    const int tid = threadIdx.x;

    float* __restrict__ orow  = out + (size_t)b * VOCAB;
    float* __restrict__ slice = orow + lo;

    // Phase 1: zero this CTA's exclusive 32000B slice, L2-allocating.
    // BINS/4 = 2000 float4 stores over 256 threads.
    #pragma unroll
    for (int i = tid; i < BINS / 4; i += NTHREADS) {
        asm volatile(
            "st.global.cg.v4.f32 [%0], {%1, %2, %3, %4};"
            :: "l"(reinterpret_cast<float4*>(slice) + i),
               "f"(0.f), "f"(0.f), "f"(0.f), "f"(0.f)
            : "memory");
    }
    __syncthreads();
    __threadfence();   // ensure our zeroes are visible at L2 before our REDs

    // Phase 2: scan the full row, RED.ADD.F32 tokens in our slice.
    const int4* __restrict__ trow = tokens4 + (size_t)b * vecs_per_row;
    #pragma unroll 2
    for (int i = tid; i < vecs_per_row; i += NTHREADS) {
        int4 t = trow[i];
        unsigned x;
        x = (unsigned)(t.x - lo); if (t.x != 0 && x < (unsigned)BINS) atomicAdd(&slice[x], 1.0f);
        x = (unsigned)(t.y - lo); if (t.y != 0 && x < (unsigned)BINS) atomicAdd(&slice[x], 1.0f);
        x = (unsigned)(t.z - lo); if (t.z != 0 && x < (unsigned)BINS) atomicAdd(&slice[x], 1.0f);
        x = (unsigned)(t.w - lo); if (t.w != 0 && x < (unsigned)BINS) atomicAdd(&slice[x], 1.0f);
    }
}

extern "C" void kernel_launch(void* const* d_in, const int* in_sizes, int n_in,
                              void* d_out, int out_size)
{
    const int* tokens = (const int*)d_in[0];   // [B, T] int32
    // d_in[1] = lengths [B] int32 — unused by the reference computation.

    const int B = in_sizes[1];                 // 256
    const int T = in_sizes[0] / B;             // 2048

    float* out = (float*)d_out;                // [B, VOCAB] float32

    onehot_zero_scatter_kernel<<<B * SPLIT, NTHREADS>>>(
        (const int4*)tokens, out, T / 4);
}